// round 1
// baseline (speedup 1.0000x reference)
#include <cuda_runtime.h>
#include <cstdint>

#define N_NODES 50000
#define N_EDGES 300000
#define MAXF 256

// ---------------- scratch (static device allocations; no cudaMalloc) ----------------
__device__ float g_sup[(size_t)N_NODES * MAXF];   // support = h @ W
__device__ float g_bufA[(size_t)N_NODES * MAXF];  // l1 / skip-sum temp
__device__ float g_bufB[(size_t)N_NODES * MAXF];  // l2 / l5
__device__ float g_l3[(size_t)N_NODES * MAXF];
__device__ float g_l4[(size_t)N_NODES * MAXF];

__device__ int   g_deg[N_NODES];
__device__ int   g_cur[N_NODES];
__device__ int   g_off[N_NODES + 1];
__device__ int   g_srcs[N_EDGES];     // src sorted by dst
__device__ float g_ws[N_EDGES];       // weight sorted by dst

// ---------------- CSR build ----------------
__global__ void k_zero_counts() {
    int i = blockIdx.x * blockDim.x + threadIdx.x;
    if (i < N_NODES) { g_deg[i] = 0; g_cur[i] = 0; }
}

__global__ void k_count(const int* __restrict__ dst) {
    int e = blockIdx.x * blockDim.x + threadIdx.x;
    if (e < N_EDGES) atomicAdd(&g_deg[dst[e]], 1);
}

// single-block exclusive scan over g_deg -> g_off
__global__ void k_scan() {
    __shared__ int sh[1024];
    __shared__ int carry;
    int tid = threadIdx.x;
    if (tid == 0) carry = 0;
    __syncthreads();
    for (int base = 0; base < N_NODES; base += 1024) {
        int i = base + tid;
        int v = (i < N_NODES) ? g_deg[i] : 0;
        sh[tid] = v;
        __syncthreads();
        #pragma unroll
        for (int ofs = 1; ofs < 1024; ofs <<= 1) {
            int t = (tid >= ofs) ? sh[tid - ofs] : 0;
            __syncthreads();
            sh[tid] += t;
            __syncthreads();
        }
        int c = carry;
        if (i < N_NODES) g_off[i] = c + sh[tid] - v;
        __syncthreads();
        if (tid == 0) carry = c + sh[1023];
        __syncthreads();
    }
    if (tid == 0) g_off[N_NODES] = carry;
}

__global__ void k_fill(const int* __restrict__ src, const int* __restrict__ dst,
                       const float* __restrict__ w) {
    int e = blockIdx.x * blockDim.x + threadIdx.x;
    if (e < N_EDGES) {
        int d = dst[e];
        int pos = g_off[d] + atomicAdd(&g_cur[d], 1);
        g_srcs[pos] = src[e];
        g_ws[pos]   = w[e];
    }
}

// ---------------- GEMM: C[M,Nd] = A[M,K] @ B[K,Nd] (fp32, 128x128x16 tiles) --------
#define BM 128
#define BN 128
#define BK 16
#define ASTRIDE (BM + 4)

__global__ __launch_bounds__(256) void k_gemm(const float* __restrict__ A,
                                              const float* __restrict__ B,
                                              float* __restrict__ C,
                                              int M, int K, int Nd) {
    __shared__ float As[BK][ASTRIDE];
    __shared__ float Bs[BK][BN];

    int tid = threadIdx.x;
    int tx = tid & 15;          // 0..15 -> 8 cols each
    int ty = tid >> 4;          // 0..15 -> 8 rows each
    int row0 = blockIdx.x * BM;
    int col0 = blockIdx.y * BN;

    float acc[8][8];
    #pragma unroll
    for (int i = 0; i < 8; i++)
        #pragma unroll
        for (int j = 0; j < 8; j++) acc[i][j] = 0.f;

    for (int k0 = 0; k0 < K; k0 += BK) {
        // load A tile (128x16) via float4 along k
        #pragma unroll
        for (int t = 0; t < 2; t++) {
            int idx = tid + t * 256;          // 0..511
            int kq = idx & 3;                 // 0..3
            int m  = idx >> 2;                // 0..127
            int gm = row0 + m;
            float4 va = make_float4(0.f, 0.f, 0.f, 0.f);
            if (gm < M)
                va = *reinterpret_cast<const float4*>(&A[(size_t)gm * K + k0 + kq * 4]);
            As[kq * 4 + 0][m] = va.x;
            As[kq * 4 + 1][m] = va.y;
            As[kq * 4 + 2][m] = va.z;
            As[kq * 4 + 3][m] = va.w;
        }
        // load B tile (16x128) via float4 along n
        #pragma unroll
        for (int t = 0; t < 2; t++) {
            int idx = tid + t * 256;          // 0..511
            int nq = idx & 31;                // 0..31 (x4 floats)
            int kr = idx >> 5;                // 0..15
            float4 vb = make_float4(0.f, 0.f, 0.f, 0.f);
            int gc = col0 + nq * 4;
            if (gc < Nd)
                vb = *reinterpret_cast<const float4*>(&B[(size_t)(k0 + kr) * Nd + gc]);
            *reinterpret_cast<float4*>(&Bs[kr][nq * 4]) = vb;
        }
        __syncthreads();

        #pragma unroll
        for (int kk = 0; kk < BK; kk++) {
            float4 a0 = *reinterpret_cast<const float4*>(&As[kk][ty * 8]);
            float4 a1 = *reinterpret_cast<const float4*>(&As[kk][ty * 8 + 4]);
            float4 b0 = *reinterpret_cast<const float4*>(&Bs[kk][tx * 8]);
            float4 b1 = *reinterpret_cast<const float4*>(&Bs[kk][tx * 8 + 4]);
            float a[8] = {a0.x, a0.y, a0.z, a0.w, a1.x, a1.y, a1.z, a1.w};
            float b[8] = {b0.x, b0.y, b0.z, b0.w, b1.x, b1.y, b1.z, b1.w};
            #pragma unroll
            for (int i = 0; i < 8; i++)
                #pragma unroll
                for (int j = 0; j < 8; j++)
                    acc[i][j] += a[i] * b[j];
        }
        __syncthreads();
    }

    // store
    #pragma unroll
    for (int i = 0; i < 8; i++) {
        int gm = row0 + ty * 8 + i;
        if (gm >= M) continue;
        int gc = col0 + tx * 8;
        if (gc < Nd) {   // Nd is a multiple of 8, so gc..gc+7 all valid
            float4 c0 = make_float4(acc[i][0], acc[i][1], acc[i][2], acc[i][3]);
            float4 c1 = make_float4(acc[i][4], acc[i][5], acc[i][6], acc[i][7]);
            *reinterpret_cast<float4*>(&C[(size_t)gm * Nd + gc])     = c0;
            *reinterpret_cast<float4*>(&C[(size_t)gm * Nd + gc + 4]) = c1;
        }
    }
}

// ---------------- aggregation: out[v,:] = relu(b + sum_e w_e * sup[src_e,:]) -------
// blockDim.x = F/4 (float4 lanes), blockDim.y = nodes per block
__global__ void k_agg(const float* __restrict__ sup, const float* __restrict__ bias,
                      float* __restrict__ out, int F) {
    int fx = threadIdx.x;                                 // float4 index
    int v  = blockIdx.x * blockDim.y + threadIdx.y;
    if (v >= N_NODES) return;
    int beg = g_off[v];
    int end = g_off[v + 1];
    float4 acc = *reinterpret_cast<const float4*>(&bias[fx * 4]);
    for (int e = beg; e < end; e++) {
        int s   = g_srcs[e];
        float w = g_ws[e];
        float4 m = *reinterpret_cast<const float4*>(&sup[(size_t)s * F + fx * 4]);
        acc.x += w * m.x;
        acc.y += w * m.y;
        acc.z += w * m.z;
        acc.w += w * m.w;
    }
    acc.x = fmaxf(acc.x, 0.f);
    acc.y = fmaxf(acc.y, 0.f);
    acc.z = fmaxf(acc.z, 0.f);
    acc.w = fmaxf(acc.w, 0.f);
    *reinterpret_cast<float4*>(&out[(size_t)v * F + fx * 4]) = acc;
}

// ---------------- elementwise adds for skip connections (F = 256) ------------------
__global__ void k_add2(const float* __restrict__ a, const float* __restrict__ b,
                       float* __restrict__ o, int n4) {
    int i = blockIdx.x * blockDim.x + threadIdx.x;
    if (i < n4) {
        float4 x = reinterpret_cast<const float4*>(a)[i];
        float4 y = reinterpret_cast<const float4*>(b)[i];
        x.x += y.x; x.y += y.y; x.z += y.z; x.w += y.w;
        reinterpret_cast<float4*>(o)[i] = x;
    }
}

__global__ void k_add3(const float* __restrict__ a, const float* __restrict__ b,
                       const float* __restrict__ c, float* __restrict__ o, int n4) {
    int i = blockIdx.x * blockDim.x + threadIdx.x;
    if (i < n4) {
        float4 x = reinterpret_cast<const float4*>(a)[i];
        float4 y = reinterpret_cast<const float4*>(b)[i];
        float4 z = reinterpret_cast<const float4*>(c)[i];
        x.x += y.x + z.x; x.y += y.y + z.y; x.z += y.z + z.z; x.w += y.w + z.w;
        reinterpret_cast<float4*>(o)[i] = x;
    }
}

// ---------------- host-side helpers ----------------
static void run_gemm(const float* A, const float* B, float* C, int M, int K, int Nd) {
    dim3 grid((M + BM - 1) / BM, (Nd + BN - 1) / BN);
    k_gemm<<<grid, 256>>>(A, B, C, M, K, Nd);
}

static void run_agg(const float* sup, const float* bias, float* out, int F) {
    int bx = F / 4;                 // 16 / 32 / 64
    int by = 256 / bx;              // 16 / 8  / 4
    dim3 block(bx, by);
    dim3 grid((N_NODES + by - 1) / by);
    k_agg<<<grid, block>>>(sup, bias, out, F);
}

extern "C" void kernel_launch(void* const* d_in, const int* in_sizes, int n_in,
                              void* d_out, int out_size) {
    const float* x  = (const float*)d_in[0];
    const int* esrc = (const int*)d_in[1];
    const int* edst = (const int*)d_in[2];
    const float* ew = (const float*)d_in[3];
    const float* W[6];
    const float* b[6];
    for (int i = 0; i < 6; i++) {
        W[i] = (const float*)d_in[4 + 2 * i];
        b[i] = (const float*)d_in[5 + 2 * i];
    }
    float* out = (float*)d_out;

    float* sup  = nullptr; float* bufA = nullptr; float* bufB = nullptr;
    float* l3   = nullptr; float* l4   = nullptr;
    cudaGetSymbolAddress((void**)&sup,  g_sup);
    cudaGetSymbolAddress((void**)&bufA, g_bufA);
    cudaGetSymbolAddress((void**)&bufB, g_bufB);
    cudaGetSymbolAddress((void**)&l3,   g_l3);
    cudaGetSymbolAddress((void**)&l4,   g_l4);

    // ---- CSR build (dst-sorted edges) ----
    k_zero_counts<<<(N_NODES + 255) / 256, 256>>>();
    k_count<<<(N_EDGES + 255) / 256, 256>>>(edst);
    k_scan<<<1, 1024>>>();
    k_fill<<<(N_EDGES + 255) / 256, 256>>>(esrc, edst, ew);

    const int n4 = N_NODES * 256 / 4;

    // L1: [N,128] @ [128,64] -> agg(64) -> bufA
    run_gemm(x, W[0], sup, N_NODES, 128, 64);
    run_agg(sup, b[0], bufA, 64);

    // L2: [N,64] @ [64,128] -> agg(128) -> bufB
    run_gemm(bufA, W[1], sup, N_NODES, 64, 128);
    run_agg(sup, b[1], bufB, 128);

    // L3: [N,128] @ [128,256] -> agg(256) -> l3
    run_gemm(bufB, W[2], sup, N_NODES, 128, 256);
    run_agg(sup, b[2], l3, 256);

    // L4: [N,256] @ [256,256] -> agg(256) -> l4
    run_gemm(l3, W[3], sup, N_NODES, 256, 256);
    run_agg(sup, b[3], l4, 256);

    // L5: (l4 + l3) -> bufA ; gemm ; agg -> bufB (=l5)
    k_add2<<<(n4 + 255) / 256, 256>>>(l4, l3, bufA, n4);
    run_gemm(bufA, W[4], sup, N_NODES, 256, 256);
    run_agg(sup, b[4], bufB, 256);

    // L6: (l5 + l4 + l3) -> bufA ; gemm ; agg -> out
    k_add3<<<(n4 + 255) / 256, 256>>>(bufB, l4, l3, bufA, n4);
    run_gemm(bufA, W[5], sup, N_NODES, 256, 256);
    run_agg(sup, b[5], out, 256);
}

// round 4
// speedup vs baseline: 1.3401x; 1.3401x over previous
#include <cuda_runtime.h>
#include <cuda_bf16.h>
#include <cstdint>

#define N_NODES 50000
#define N_EDGES 300000
#define MAXF 256

// ---------------- scratch (static device allocations) ----------------
__device__ float g_agg[(size_t)N_NODES * MAXF];   // aggregation output / GEMM input
__device__ float g_tmp[(size_t)N_NODES * MAXF];   // skip-sum temp
__device__ float g_h12[(size_t)N_NODES * MAXF];   // l1 / l2 / l5
__device__ float g_l3[(size_t)N_NODES * MAXF];
__device__ float g_l4[(size_t)N_NODES * MAXF];
__device__ __nv_bfloat16 g_wh[256 * 256];         // W split hi, transposed to [N][K]
__device__ __nv_bfloat16 g_wl[256 * 256];         // W split lo, transposed to [N][K]

__device__ int   g_deg[N_NODES];
__device__ int   g_cur[N_NODES];
__device__ int   g_off[N_NODES + 1];
__device__ int   g_srcs[N_EDGES];
__device__ float g_ws[N_EDGES];

// ---------------- CSR build ----------------
__global__ void k_zero_counts() {
    int i = blockIdx.x * blockDim.x + threadIdx.x;
    if (i < N_NODES) { g_deg[i] = 0; g_cur[i] = 0; }
}
__global__ void k_count(const int* __restrict__ dst) {
    int e = blockIdx.x * blockDim.x + threadIdx.x;
    if (e < N_EDGES) atomicAdd(&g_deg[dst[e]], 1);
}
__global__ void k_scan() {
    __shared__ int sh[1024];
    __shared__ int carry;
    int tid = threadIdx.x;
    if (tid == 0) carry = 0;
    __syncthreads();
    for (int base = 0; base < N_NODES; base += 1024) {
        int i = base + tid;
        int v = (i < N_NODES) ? g_deg[i] : 0;
        sh[tid] = v;
        __syncthreads();
        #pragma unroll
        for (int ofs = 1; ofs < 1024; ofs <<= 1) {
            int t = (tid >= ofs) ? sh[tid - ofs] : 0;
            __syncthreads();
            sh[tid] += t;
            __syncthreads();
        }
        int c = carry;
        if (i < N_NODES) g_off[i] = c + sh[tid] - v;
        __syncthreads();
        if (tid == 0) carry = c + sh[1023];
        __syncthreads();
    }
    if (tid == 0) g_off[N_NODES] = carry;
}
__global__ void k_fill(const int* __restrict__ src, const int* __restrict__ dst,
                       const float* __restrict__ w) {
    int e = blockIdx.x * blockDim.x + threadIdx.x;
    if (e < N_EDGES) {
        int d = dst[e];
        int pos = g_off[d] + atomicAdd(&g_cur[d], 1);
        g_srcs[pos] = src[e];
        g_ws[pos]   = w[e];
    }
}

// ---------------- W split: g_wh/g_wl[n*K+k] = split(W[k*N+n]) ----------------
__global__ void k_splitW(const float* __restrict__ W, int K, int Nd) {
    int i = blockIdx.x * blockDim.x + threadIdx.x;
    if (i < K * Nd) {
        int k = i / Nd, n = i % Nd;
        float v = W[i];
        __nv_bfloat16 h = __float2bfloat16(v);
        float r = v - __bfloat162float(h);
        g_wh[n * K + k] = h;
        g_wl[n * K + k] = __float2bfloat16(r);
    }
}

// ---------------- mma.sync helpers ----------------
__device__ __forceinline__ void ldm_x4(uint32_t* r, uint32_t addr) {
    asm volatile("ldmatrix.sync.aligned.m8n8.x4.shared.b16 {%0,%1,%2,%3}, [%4];"
        : "=r"(r[0]), "=r"(r[1]), "=r"(r[2]), "=r"(r[3]) : "r"(addr));
}
__device__ __forceinline__ void ldm_x2(uint32_t* r, uint32_t addr) {
    asm volatile("ldmatrix.sync.aligned.m8n8.x2.shared.b16 {%0,%1}, [%2];"
        : "=r"(r[0]), "=r"(r[1]) : "r"(addr));
}
__device__ __forceinline__ void mma_bf16(float* d, const uint32_t* a, const uint32_t* b) {
    asm volatile(
        "mma.sync.aligned.m16n8k16.row.col.f32.bf16.bf16.f32 "
        "{%0,%1,%2,%3}, {%4,%5,%6,%7}, {%8,%9}, {%0,%1,%2,%3};"
        : "+f"(d[0]), "+f"(d[1]), "+f"(d[2]), "+f"(d[3])
        : "r"(a[0]), "r"(a[1]), "r"(a[2]), "r"(a[3]), "r"(b[0]), "r"(b[1]));
}
__device__ __forceinline__ uint32_t smem_u32(const void* p) {
    uint32_t a;
    asm("{ .reg .u64 t; cvta.to.shared.u64 t, %1; cvt.u32.u64 %0, t; }" : "=r"(a) : "l"(p));
    return a;
}
__device__ __forceinline__ uint32_t pack_bf16x2(float a, float b) {
    __nv_bfloat162 t = __floats2bfloat162_rn(a, b);
    return *reinterpret_cast<uint32_t*>(&t);
}

// ---------------- tensor-core GEMM: C = relu(A[M,K] @ W[K,N] + bias) -------------
// bf16 3-pass split (Ah*Bh + Al*Bh + Ah*Bl), fp32 accum.
// CTA: 128x128 tile; 8 warps as 2(m) x 4(n), warp tile 64x32; K chunk = 32.
#define ASTR 40   // smem row stride in bf16 elems (conflict-free for ldmatrix)

__global__ __launch_bounds__(256) void k_gemm_mma(
    const float* __restrict__ A,
    const __nv_bfloat16* __restrict__ Bh,
    const __nv_bfloat16* __restrict__ Bl,
    const float* __restrict__ bias,
    float* __restrict__ C,
    int M, int K, int Nd)
{
    __shared__ __nv_bfloat16 sAh[128][ASTR];
    __shared__ __nv_bfloat16 sAl[128][ASTR];
    __shared__ __nv_bfloat16 sBh[128][ASTR];
    __shared__ __nv_bfloat16 sBl[128][ASTR];

    const int tid = threadIdx.x;
    const int wid = tid >> 5;
    const int lane = tid & 31;
    const int wm = wid >> 2;          // 0..1 -> m offset 64*wm
    const int wn = wid & 3;           // 0..3 -> n offset 32*wn
    const int row0 = blockIdx.x * 128;
    const int col0 = blockIdx.y * 128;

    const uint32_t sAh_b = smem_u32(&sAh[0][0]);
    const uint32_t sAl_b = smem_u32(&sAl[0][0]);
    const uint32_t sBh_b = smem_u32(&sBh[0][0]);
    const uint32_t sBl_b = smem_u32(&sBl[0][0]);

    float acc[4][4][4];
    #pragma unroll
    for (int i = 0; i < 4; i++)
        #pragma unroll
        for (int j = 0; j < 4; j++)
            #pragma unroll
            for (int q = 0; q < 4; q++) acc[i][j][q] = 0.f;

    // ldmatrix lane address components
    const int a_r = (lane & 7) + ((lane >> 3) & 1) * 8;  // row within 16
    const int a_k = (lane >> 4) * 8;                     // k offset 0/8
    const int b_r = lane & 7;                            // n row within 8
    const int b_k = ((lane >> 3) & 1) * 8;               // k offset 0/8 (lanes 0-15)

    const int nchunks = K >> 5;
    for (int c = 0; c < nchunks; c++) {
        const int k0 = c << 5;
        // ---- A tile: 128x32 fp32 -> bf16 hi/lo ----
        #pragma unroll
        for (int t = 0; t < 4; t++) {
            int idx = tid + t * 256;          // 0..1023
            int row = idx >> 3;
            int q = idx & 7;                  // float4 within row of 32
            int gm = row0 + row;
            float4 v = make_float4(0.f, 0.f, 0.f, 0.f);
            if (gm < M)
                v = *reinterpret_cast<const float4*>(&A[(size_t)gm * K + k0 + q * 4]);
            __nv_bfloat162 h01 = __floats2bfloat162_rn(v.x, v.y);
            __nv_bfloat162 h23 = __floats2bfloat162_rn(v.z, v.w);
            uint2 hi = make_uint2(*reinterpret_cast<uint32_t*>(&h01),
                                  *reinterpret_cast<uint32_t*>(&h23));
            uint2 lo = make_uint2(
                pack_bf16x2(v.x - __bfloat162float(h01.x), v.y - __bfloat162float(h01.y)),
                pack_bf16x2(v.z - __bfloat162float(h23.x), v.w - __bfloat162float(h23.y)));
            *reinterpret_cast<uint2*>(&sAh[row][q * 4]) = hi;
            *reinterpret_cast<uint2*>(&sAl[row][q * 4]) = lo;
        }
        // ---- B tile: 128 n-rows x 32 k (bf16, pre-split [N][K]) ----
        #pragma unroll
        for (int t = 0; t < 2; t++) {
            int idx = tid + t * 256;          // 0..511
            int row = idx >> 2;               // local n
            int q = idx & 3;                  // uint4 (8 bf16) within row
            int gn = col0 + row;
            uint4 vh = make_uint4(0u, 0u, 0u, 0u);
            uint4 vl = make_uint4(0u, 0u, 0u, 0u);
            if (gn < Nd) {
                vh = *reinterpret_cast<const uint4*>(&Bh[(size_t)gn * K + k0 + q * 8]);
                vl = *reinterpret_cast<const uint4*>(&Bl[(size_t)gn * K + k0 + q * 8]);
            }
            *reinterpret_cast<uint4*>(&sBh[row][q * 8]) = vh;
            *reinterpret_cast<uint4*>(&sBl[row][q * 8]) = vl;
        }
        __syncthreads();

        #pragma unroll
        for (int ks = 0; ks < 2; ks++) {
            const int kb = ks * 16;
            uint32_t ah[4][4], al[4][4], bh[4][2], bl[4][2];
            #pragma unroll
            for (int mt = 0; mt < 4; mt++) {
                uint32_t off = ((wm * 64 + mt * 16 + a_r) * ASTR + kb + a_k) * 2;
                ldm_x4(ah[mt], sAh_b + off);
                ldm_x4(al[mt], sAl_b + off);
            }
            #pragma unroll
            for (int nt = 0; nt < 4; nt++) {
                uint32_t off = ((wn * 32 + nt * 8 + b_r) * ASTR + kb + b_k) * 2;
                ldm_x2(bh[nt], sBh_b + off);
                ldm_x2(bl[nt], sBl_b + off);
            }
            #pragma unroll
            for (int mt = 0; mt < 4; mt++)
                #pragma unroll
                for (int nt = 0; nt < 4; nt++)
                    mma_bf16(acc[mt][nt], ah[mt], bh[nt]);
            #pragma unroll
            for (int mt = 0; mt < 4; mt++)
                #pragma unroll
                for (int nt = 0; nt < 4; nt++)
                    mma_bf16(acc[mt][nt], al[mt], bh[nt]);
            #pragma unroll
            for (int mt = 0; mt < 4; mt++)
                #pragma unroll
                for (int nt = 0; nt < 4; nt++)
                    mma_bf16(acc[mt][nt], ah[mt], bl[nt]);
        }
        __syncthreads();
    }

    // ---- epilogue: bias + relu ----
    #pragma unroll
    for (int mt = 0; mt < 4; mt++) {
        #pragma unroll
        for (int nt = 0; nt < 4; nt++) {
            int col = col0 + wn * 32 + nt * 8 + (lane & 3) * 2;
            if (col >= Nd) continue;
            float b0 = bias[col], b1 = bias[col + 1];
            int r0 = row0 + wm * 64 + mt * 16 + (lane >> 2);
            if (r0 < M) {
                float2 v = make_float2(fmaxf(acc[mt][nt][0] + b0, 0.f),
                                       fmaxf(acc[mt][nt][1] + b1, 0.f));
                *reinterpret_cast<float2*>(&C[(size_t)r0 * Nd + col]) = v;
            }
            int r1 = r0 + 8;
            if (r1 < M) {
                float2 v = make_float2(fmaxf(acc[mt][nt][2] + b0, 0.f),
                                       fmaxf(acc[mt][nt][3] + b1, 0.f));
                *reinterpret_cast<float2*>(&C[(size_t)r1 * Nd + col]) = v;
            }
        }
    }
}

// ---------------- aggregation: out[v,:] = sum_e w_e * h[src_e,:] ----------------
__global__ void k_agg(const float* __restrict__ h, float* __restrict__ out, int F) {
    int fx = threadIdx.x;
    int v  = blockIdx.x * blockDim.y + threadIdx.y;
    if (v >= N_NODES) return;
    int beg = g_off[v];
    int end = g_off[v + 1];
    float4 acc = make_float4(0.f, 0.f, 0.f, 0.f);
    for (int e = beg; e < end; e++) {
        int s   = g_srcs[e];
        float w = g_ws[e];
        float4 m = *reinterpret_cast<const float4*>(&h[(size_t)s * F + fx * 4]);
        acc.x += w * m.x;
        acc.y += w * m.y;
        acc.z += w * m.z;
        acc.w += w * m.w;
    }
    *reinterpret_cast<float4*>(&out[(size_t)v * F + fx * 4]) = acc;
}

// ---------------- skip adds ----------------
__global__ void k_add2(const float* __restrict__ a, const float* __restrict__ b,
                       float* __restrict__ o, int n4) {
    int i = blockIdx.x * blockDim.x + threadIdx.x;
    if (i < n4) {
        float4 x = reinterpret_cast<const float4*>(a)[i];
        float4 y = reinterpret_cast<const float4*>(b)[i];
        x.x += y.x; x.y += y.y; x.z += y.z; x.w += y.w;
        reinterpret_cast<float4*>(o)[i] = x;
    }
}
__global__ void k_add3(const float* __restrict__ a, const float* __restrict__ b,
                       const float* __restrict__ c, float* __restrict__ o, int n4) {
    int i = blockIdx.x * blockDim.x + threadIdx.x;
    if (i < n4) {
        float4 x = reinterpret_cast<const float4*>(a)[i];
        float4 y = reinterpret_cast<const float4*>(b)[i];
        float4 z = reinterpret_cast<const float4*>(c)[i];
        x.x += y.x + z.x; x.y += y.y + z.y; x.z += y.z + z.z; x.w += y.w + z.w;
        reinterpret_cast<float4*>(o)[i] = x;
    }
}

// ---------------- host helpers ----------------
static void run_agg(const float* h, float* out, int F) {
    int bx = F / 4;
    int by = 256 / bx;
    dim3 block(bx, by);
    dim3 grid((N_NODES + by - 1) / by);
    k_agg<<<grid, block>>>(h, out, F);
}

static void run_gemm_tc(const float* A, const float* W, const float* bias,
                        float* C, int K, int Nd,
                        const __nv_bfloat16* wh, const __nv_bfloat16* wl) {
    k_splitW<<<(K * Nd + 255) / 256, 256>>>(W, K, Nd);
    dim3 grid((N_NODES + 127) / 128, (Nd + 127) / 128);
    k_gemm_mma<<<grid, 256>>>(A, wh, wl, bias, C, N_NODES, K, Nd);
}

extern "C" void kernel_launch(void* const* d_in, const int* in_sizes, int n_in,
                              void* d_out, int out_size) {
    const float* x  = (const float*)d_in[0];
    const int* esrc = (const int*)d_in[1];
    const int* edst = (const int*)d_in[2];
    const float* ew = (const float*)d_in[3];
    const float* W[6];
    const float* b[6];
    for (int i = 0; i < 6; i++) {
        W[i] = (const float*)d_in[4 + 2 * i];
        b[i] = (const float*)d_in[5 + 2 * i];
    }
    float* out = (float*)d_out;

    float* aggb = nullptr; float* tmp = nullptr; float* h12 = nullptr;
    float* l3 = nullptr; float* l4 = nullptr;
    __nv_bfloat16* wh = nullptr; __nv_bfloat16* wl = nullptr;
    cudaGetSymbolAddress((void**)&aggb, g_agg);
    cudaGetSymbolAddress((void**)&tmp,  g_tmp);
    cudaGetSymbolAddress((void**)&h12,  g_h12);
    cudaGetSymbolAddress((void**)&l3,   g_l3);
    cudaGetSymbolAddress((void**)&l4,   g_l4);
    cudaGetSymbolAddress((void**)&wh,   g_wh);
    cudaGetSymbolAddress((void**)&wl,   g_wl);

    // ---- CSR build ----
    k_zero_counts<<<(N_NODES + 255) / 256, 256>>>();
    k_count<<<(N_EDGES + 255) / 256, 256>>>(edst);
    k_scan<<<1, 1024>>>();
    k_fill<<<(N_EDGES + 255) / 256, 256>>>(esrc, edst, ew);

    const int n4 = N_NODES * 256 / 4;

    // L1: agg(x)[128] @ W1 -> l1[64]            (h12)
    run_agg(x, aggb, 128);
    run_gemm_tc(aggb, W[0], b[0], h12, 128, 64, wh, wl);

    // L2: agg(l1)[64] @ W2 -> l2[128]           (h12)
    run_agg(h12, aggb, 64);
    run_gemm_tc(aggb, W[1], b[1], h12, 64, 128, wh, wl);

    // L3: agg(l2)[128] @ W3 -> l3[256]
    run_agg(h12, aggb, 128);
    run_gemm_tc(aggb, W[2], b[2], l3, 128, 256, wh, wl);

    // L4: agg(l3)[256] @ W4 -> l4[256]
    run_agg(l3, aggb, 256);
    run_gemm_tc(aggb, W[3], b[3], l4, 256, 256, wh, wl);

    // L5: agg(l4+l3)[256] @ W5 -> l5            (h12)
    k_add2<<<(n4 + 255) / 256, 256>>>(l4, l3, tmp, n4);
    run_agg(tmp, aggb, 256);
    run_gemm_tc(aggb, W[4], b[4], h12, 256, 256, wh, wl);

    // L6: agg(l5+l4+l3)[256] @ W6 -> out
    k_add3<<<(n4 + 255) / 256, 256>>>(h12, l4, l3, tmp, n4);
    run_agg(tmp, aggb, 256);
    run_gemm_tc(aggb, W[5], b[5], out, 256, 256, wh, wl);
}